// round 16
// baseline (speedup 1.0000x reference)
#include <cuda_runtime.h>
#include <cuda_fp16.h>
#include <cstdint>
#include <math.h>

// Problem constants
#define T_ 512
#define E_ 8
#define H_ 2048
#define I_ 5632
#define A_ (2 * T_)   // 1024 token-expert assignments (top_k = 2)
#define SPLITK 4
#define K2_PER (I_ / SPLITK)   // 1408

// ---------------- scratch (device globals; no allocation allowed) ----------------
__device__ __half g_xh[(size_t)T_ * H_];            // x converted to fp16
__device__ __half g_acth[(size_t)A_ * I_];          // SwiGLU activations fp16, perm order
__device__ float  g_part[(size_t)SPLITK * A_ * H_]; // split-K partials of down-proj
__device__ int    g_perm[A_];                       // assignment ids grouped by expert
__device__ int    g_offs[E_ + 1];                   // expert segment offsets
__device__ float  g_aw[A_];                         // renormalized top-2 weights

// ---------------- helpers ----------------
__device__ __forceinline__ uint32_t pack_h2(float2 v) {  // {lo=v.x, hi=v.y} as f16x2
    uint32_t r;
    asm("cvt.rn.f16x2.f32 %0, %1, %2;" : "=r"(r) : "f"(v.y), "f"(v.x));
    return r;
}
__device__ __forceinline__ void mma_f16(float* d, const uint32_t* a, const uint32_t* b) {
    asm volatile(
        "mma.sync.aligned.m16n8k16.row.col.f32.f16.f16.f32 "
        "{%0,%1,%2,%3}, {%4,%5,%6,%7}, {%8,%9}, {%0,%1,%2,%3};"
        : "+f"(d[0]), "+f"(d[1]), "+f"(d[2]), "+f"(d[3])
        : "r"(a[0]), "r"(a[1]), "r"(a[2]), "r"(a[3]), "r"(b[0]), "r"(b[1]));
}
__device__ __forceinline__ void ldsm_x4(uint32_t* r, uint32_t addr) {
    asm volatile("ldmatrix.sync.aligned.m8n8.x4.shared.b16 {%0,%1,%2,%3}, [%4];"
                 : "=r"(r[0]), "=r"(r[1]), "=r"(r[2]), "=r"(r[3]) : "r"(addr));
}
__device__ __forceinline__ uint32_t smem_u32(const void* p) {
    return (uint32_t)__cvta_generic_to_shared(p);
}
#define CP_ASYNC16(dst, src) \
    asm volatile("cp.async.cg.shared.global [%0], [%1], 16;" :: "r"(dst), "l"(src))
#define CP_COMMIT() asm volatile("cp.async.commit_group;" ::: "memory")
#define CP_WAIT(n)  asm volatile("cp.async.wait_group %0;" :: "n"(n) : "memory")

// B tile swizzle: chunk q of row n stored at position q ^ ((n&3)<<1) -> conflict-free
// LDS.64 fragment reads.
__device__ __forceinline__ uint32_t tswz(int row, int k) {
    return (uint32_t)(row * 128 + (((k >> 2) ^ ((row & 3) << 1)) << 4) + ((k & 3) << 2));
}
__device__ __forceinline__ float2 lds2(const char* base, int row, int k) {
    return *(const float2*)(base + tswz(row, k));
}

// fp16 A subtile: 128 rows x 32 halves, padded row stride 80B (conflict-free)
#define AROW 80
#define A_SUB 10240     // one 32-K A subtile
// B subtile: 256 rows x 128B = 32 KB (one 32-K slice)
#define B_SUB 32768
// Stage = K=64: A0|A1|B0|B1
#define STG (2 * A_SUB + 2 * B_SUB)   // 86016
#define NSTG 2
#define GM_SMEM (NSTG * STG + 512)    // 172544

#define NT 512   // threads per GEMM CTA (16 warps: 2M x 8N, warp tile 64x32)

// Mainloop macro: MTCOND is the per-mt-block activity predicate (warp-uniform).
// Full-tile path instantiates MTCOND=1 (constant-folds to the unguarded loop).
#define MAINLOOP(NSV, MTCOND)                                                     \
    for (int s = 0; s < (NSV); s++) {                                             \
        CP_WAIT(0);                                                               \
        __syncthreads();                                                          \
        if (s + 1 < (NSV)) issue(s + 1);                                          \
        CP_COMMIT();                                                              \
        const uint32_t st = smbase + (uint32_t)(s & 1) * STG;                     \
        const char* Bb = sm + (s & 1) * STG + 2 * A_SUB;                          \
        _Pragma("unroll")                                                         \
        for (int kt = 0; kt < 4; kt++) {                                          \
            const int ksub = kt >> 1, kk = kt & 1;                                \
            uint32_t af[4][4], bf[4][2];                                          \
            const uint32_t Abase = st + (uint32_t)ksub * A_SUB;                   \
            _Pragma("unroll")                                                     \
            for (int mt = 0; mt < 4; mt++)                                        \
                if (MTCOND)                                                       \
                    ldsm_x4(af[mt], Abase + lmoff + (uint32_t)(mt * 16 * AROW + kk * 32)); \
            const char* B = Bb + ksub * B_SUB;                                    \
            const int k0 = kk * 16 + 2 * tig;                                     \
            _Pragma("unroll")                                                     \
            for (int nt = 0; nt < 4; nt++) {                                      \
                int n = wn * 32 + nt * 8 + gid;                                   \
                bf[nt][0] = pack_h2(lds2(B, n, k0));                              \
                bf[nt][1] = pack_h2(lds2(B, n, k0 + 8));                          \
            }                                                                     \
            _Pragma("unroll")                                                     \
            for (int mt = 0; mt < 4; mt++)                                        \
                if (MTCOND) {                                                     \
                    _Pragma("unroll")                                             \
                    for (int nt = 0; nt < 4; nt++)                                \
                        mma_f16(c[mt][nt], af[mt], bf[nt]);                       \
                }                                                                 \
        }                                                                         \
    }

// ---------------- x -> fp16 ----------------
__global__ void xcvt_kernel(const float* __restrict__ x) {
    int i = blockIdx.x * blockDim.x + threadIdx.x;   // over T_*H_/2 half2
    float2 v = *(const float2*)&x[2 * i];
    *(uint32_t*)&g_xh[2 * i] = pack_h2(v);
}

// ---------------- routing ----------------
__global__ void route_kernel(const float* __restrict__ logits) {
    __shared__ unsigned char s_e[A_];
    __shared__ int s_cnt[E_];
    __shared__ int s_off[E_ + 1];

    int t = threadIdx.x;
    if (t < E_) s_cnt[t] = 0;
    __syncthreads();

    float l[E_];
#pragma unroll
    for (int e = 0; e < E_; e++) l[e] = logits[t * E_ + e];

    int e0 = 0;
#pragma unroll
    for (int e = 1; e < E_; e++) if (l[e] > l[e0]) e0 = e;
    int e1 = (e0 == 0) ? 1 : 0;
#pragma unroll
    for (int e = 0; e < E_; e++) if (e != e0 && l[e] > l[e1]) e1 = e;

    float p1 = __expf(l[e1] - l[e0]);
    float inv = 1.0f / (1.0f + p1);
    g_aw[2 * t + 0] = inv;
    g_aw[2 * t + 1] = p1 * inv;

    s_e[2 * t + 0] = (unsigned char)e0;
    s_e[2 * t + 1] = (unsigned char)e1;
    atomicAdd(&s_cnt[e0], 1);
    atomicAdd(&s_cnt[e1], 1);
    __syncthreads();

    if (t == 0) {
        int acc = 0;
        for (int e = 0; e < E_; e++) { s_off[e] = acc; acc += s_cnt[e]; }
        s_off[E_] = acc;
        for (int e = 0; e <= E_; e++) g_offs[e] = s_off[e];
    }
    __syncthreads();

#pragma unroll
    for (int k = 0; k < 2; k++) {
        int a = 2 * t + k;
        int e = s_e[a];
        int rank = 0;
        for (int b = 0; b < a; b++) rank += (s_e[b] == e) ? 1 : 0;
        g_perm[s_off[e] + rank] = a;
    }
}

// =================================================================================
// GEMM1 fused: act[m, i0..i0+128) = silu(x@Wg^T)*(x@Wu^T). B rows interleaved g/u.
// CTA: M=128 x 256 B-rows, 16 warps = 2M x 8N, warp 64x32. K=64/stage, 2 stages.
// Dual-path mainloop: full tiles run the unguarded loop; M-tail tiles skip
// inactive 16-row mt-blocks for the whole K loop.
// =================================================================================
__global__ __launch_bounds__(NT, 1)
void gemm1_fused(const float* __restrict__ w13)
{
    constexpr int NS = H_ / 64;   // 32 stages

    extern __shared__ char sm[];
    int* s_row = (int*)(sm + NSTG * STG);

    const int e = blockIdx.z;
    const int base = g_offs[e];
    const int cnt = g_offs[e + 1] - base;
    const int m0 = blockIdx.y * 128;
    if (m0 >= cnt) return;
    const int i0 = blockIdx.x * 128;   // 128 intermediates -> 256 interleaved B rows
    const int mrem = cnt - m0;

    const int tid = threadIdx.x;
    const int wid = tid >> 5, lid = tid & 31;
    const int gid = lid >> 2, tig = lid & 3;
    const int wm = wid >> 3, wn = wid & 7;   // 2M x 8N, SMSP-balanced

    if (tid < 128) {
        int m = m0 + tid;
        int mm = (m < cnt) ? m : 0;
        s_row[tid] = g_perm[base + mm] >> 1;
    }
    __syncthreads();

    const uint32_t lmoff =
        (uint32_t)((wm * 64 + (lid & 7) + ((lid >> 3) & 1) * 8) * AROW + ((lid >> 4) & 1) * 16);

    // A: 512 chunks/subtile -> 1/thread.  B: 2048 chunks/subtile -> 4/thread.
    const char* ap; uint32_t soA;
    const float* bp[4]; uint32_t soB[4];
    {
        int row = tid >> 2, q = tid & 3;
        soA = (uint32_t)(row * AROW + q * 16);
        ap = (const char*)(g_xh + (size_t)s_row[row] * H_) + q * 16;
    }
#pragma unroll
    for (int t = 0; t < 4; t++) {
        int idx = t * NT + tid;
        int row = idx >> 3, q = idx & 7;   // smem row 0..255
        soB[t] = (uint32_t)(row * 128 + ((q ^ ((row & 3) << 1)) << 4));
        int ii = i0 + (row >> 1) + ((row & 1) ? I_ : 0);   // gate/up interleave
        bp[t] = w13 + ((size_t)e * (2 * I_) + (size_t)ii) * H_ + q * 4;
    }

    const uint32_t smbase = smem_u32(sm);
    auto issue = [&](int stage) {
        uint32_t st = smbase + (uint32_t)(stage & 1) * STG;
        CP_ASYNC16(st + soA, ap);
        CP_ASYNC16(st + A_SUB + soA, ap + 64);
        ap += 128;
        uint32_t bb = st + 2 * A_SUB;
#pragma unroll
        for (int t = 0; t < 4; t++) {
            CP_ASYNC16(bb + soB[t], bp[t]);
            CP_ASYNC16(bb + B_SUB + soB[t], bp[t] + 32);
            bp[t] += 64;
        }
    };

    issue(0); CP_COMMIT();

    float c[4][4][4] = {};   // 64 accum regs

    if (mrem >= 128) {
        MAINLOOP(NS, 1)
    } else {
        int mtcap = (mrem - wm * 64 + 15) >> 4;   // arith shift; clamp below
        if (mtcap < 0) mtcap = 0;
        if (mtcap > 4) mtcap = 4;
        MAINLOOP(NS, mt < mtcap)
    }

    // epilogue: (d0,d1) = (gate_j, up_j), j = i0 + wn*16 + nt*4 + tig
#pragma unroll
    for (int mt = 0; mt < 4; mt++) {
#pragma unroll
        for (int rr = 0; rr < 2; rr++) {
            int m = m0 + wm * 64 + mt * 16 + gid + rr * 8;
            if (m < cnt) {
                __half* op = g_acth + (size_t)(base + m) * I_ + (size_t)(i0 + wn * 16 + tig);
#pragma unroll
                for (int nt = 0; nt < 4; nt++) {
                    float g = c[mt][nt][2 * rr];
                    float u = c[mt][nt][2 * rr + 1];
                    op[nt * 4] = __float2half((g / (1.0f + __expf(-g))) * u);
                }
            }
        }
    }
}

// =================================================================================
// GEMM2 (split-K=4): part[sk][a, h0..h0+256) = act_fp16 @ w2^T.
// =================================================================================
__global__ __launch_bounds__(NT, 1)
void gemm2_tc(const float* __restrict__ w2)
{
    constexpr int NS = K2_PER / 64;   // 22 stages

    extern __shared__ char sm[];
    int* s_row = (int*)(sm + NSTG * STG);

    const int e  = blockIdx.z >> 2;
    const int sk = blockIdx.z & 3;
    const int base = g_offs[e];
    const int cnt = g_offs[e + 1] - base;
    const int m0 = blockIdx.y * 128;
    if (m0 >= cnt) return;
    const int n0 = blockIdx.x * 256;
    const int koff = sk * K2_PER;
    const int mrem = cnt - m0;

    const int tid = threadIdx.x;
    const int wid = tid >> 5, lid = tid & 31;
    const int gid = lid >> 2, tig = lid & 3;
    const int wm = wid >> 3, wn = wid & 7;   // 2M x 8N, SMSP-balanced

    if (tid < 128) {
        int m = m0 + tid;
        s_row[tid] = base + ((m < cnt) ? m : 0);
    }
    __syncthreads();

    const uint32_t lmoff =
        (uint32_t)((wm * 64 + (lid & 7) + ((lid >> 3) & 1) * 8) * AROW + ((lid >> 4) & 1) * 16);

    const char* ap; uint32_t soA;
    const float* bp[4]; uint32_t soB[4];
    {
        int row = tid >> 2, q = tid & 3;
        soA = (uint32_t)(row * AROW + q * 16);
        ap = (const char*)(g_acth + (size_t)s_row[row] * I_ + koff) + q * 16;
    }
#pragma unroll
    for (int t = 0; t < 4; t++) {
        int idx = t * NT + tid;
        int row = idx >> 3, q = idx & 7;   // smem row 0..255
        soB[t] = (uint32_t)(row * 128 + ((q ^ ((row & 3) << 1)) << 4));
        bp[t] = w2 + ((size_t)e * H_ + (size_t)(n0 + row)) * I_ + koff + q * 4;
    }

    const uint32_t smbase = smem_u32(sm);
    auto issue = [&](int stage) {
        uint32_t st = smbase + (uint32_t)(stage & 1) * STG;
        CP_ASYNC16(st + soA, ap);
        CP_ASYNC16(st + A_SUB + soA, ap + 64);
        ap += 128;
        uint32_t bb = st + 2 * A_SUB;
#pragma unroll
        for (int t = 0; t < 4; t++) {
            CP_ASYNC16(bb + soB[t], bp[t]);
            CP_ASYNC16(bb + B_SUB + soB[t], bp[t] + 32);
            bp[t] += 64;
        }
    };

    issue(0); CP_COMMIT();

    float c[4][4][4] = {};

    if (mrem >= 128) {
        MAINLOOP(NS, 1)
    } else {
        int mtcap = (mrem - wm * 64 + 15) >> 4;
        if (mtcap < 0) mtcap = 0;
        if (mtcap > 4) mtcap = 4;
        MAINLOOP(NS, mt < mtcap)
    }

    // epilogue: write split partial (assignment-id rows)
    float* part = g_part + (size_t)sk * A_ * H_;
#pragma unroll
    for (int mt = 0; mt < 4; mt++) {
#pragma unroll
        for (int rr = 0; rr < 2; rr++) {
            int m = m0 + wm * 64 + mt * 16 + gid + rr * 8;
            if (m < cnt) {
                int orow = g_perm[base + m];
                float* op = part + (size_t)orow * H_ + (size_t)(n0 + wn * 32) + 2 * tig;
#pragma unroll
                for (int nt = 0; nt < 4; nt++) {
                    float2 v = make_float2(c[mt][nt][2 * rr], c[mt][nt][2 * rr + 1]);
                    *(float2*)(op + nt * 8) = v;
                }
            }
        }
    }
}

// ---------------- combine: out[t,h] = sum_k aw * sum_s part[s][2t+k][h] -----------
__global__ void combine_kernel(float* __restrict__ out) {
    int idx = blockIdx.x * blockDim.x + threadIdx.x;
    int t  = idx >> 9;
    int h4 = idx & 511;
    float w0 = g_aw[2 * t];
    float w1 = g_aw[2 * t + 1];
    size_t o0 = (size_t)(2 * t) * H_ + (size_t)h4 * 4;
    size_t o1 = (size_t)(2 * t + 1) * H_ + (size_t)h4 * 4;

    float4 a0 = make_float4(0.f, 0.f, 0.f, 0.f);
    float4 a1 = make_float4(0.f, 0.f, 0.f, 0.f);
#pragma unroll
    for (int s = 0; s < SPLITK; s++) {   // fixed order -> deterministic
        const float* p = g_part + (size_t)s * A_ * H_;
        float4 v0 = *(const float4*)(p + o0);
        float4 v1 = *(const float4*)(p + o1);
        a0.x += v0.x; a0.y += v0.y; a0.z += v0.z; a0.w += v0.w;
        a1.x += v1.x; a1.y += v1.y; a1.z += v1.z; a1.w += v1.w;
    }
    float4 o;
    o.x = w0 * a0.x + w1 * a1.x;
    o.y = w0 * a0.y + w1 * a1.y;
    o.z = w0 * a0.z + w1 * a1.z;
    o.w = w0 * a0.w + w1 * a1.w;
    *(float4*)&out[(size_t)t * H_ + (size_t)h4 * 4] = o;
}

extern "C" void kernel_launch(void* const* d_in, const int* in_sizes, int n_in,
                              void* d_out, int out_size) {
    const float* x   = (const float*)d_in[0];   // [512, 2048]
    const float* rl  = (const float*)d_in[1];   // [512, 8]
    const float* w13 = (const float*)d_in[2];   // [8, 11264, 2048]
    const float* w2  = (const float*)d_in[3];   // [8, 2048, 5632]
    float* out = (float*)d_out;                 // [512, 2048]
    (void)in_sizes; (void)n_in; (void)out_size;

    cudaFuncSetAttribute(gemm1_fused, cudaFuncAttributeMaxDynamicSharedMemorySize, GM_SMEM);
    cudaFuncSetAttribute(gemm2_tc,    cudaFuncAttributeMaxDynamicSharedMemorySize, GM_SMEM);

    xcvt_kernel<<<(T_ * H_ / 2) / 256, 256>>>(x);
    route_kernel<<<1, T_>>>(rl);
    // GEMM1 fused: 44 i-tiles x 4 M-blocks x 8 experts
    gemm1_fused<<<dim3(I_ / 128, 4, E_), NT, GM_SMEM>>>(w13);
    // GEMM2 split-K: 8 h-tiles x 4 M-blocks x (e*4+sk)
    gemm2_tc<<<dim3(H_ / 256, 4, E_ * SPLITK), NT, GM_SMEM>>>(w2);
    combine_kernel<<<(T_ * H_ / 4) / 512, 512>>>(out);
}

// round 17
// speedup vs baseline: 1.0534x; 1.0534x over previous
#include <cuda_runtime.h>
#include <cuda_fp16.h>
#include <cstdint>
#include <math.h>

// Problem constants
#define T_ 512
#define E_ 8
#define H_ 2048
#define I_ 5632
#define A_ (2 * T_)   // 1024 token-expert assignments (top_k = 2)
#define SPLITK 4
#define K2_PER (I_ / SPLITK)   // 1408

// ---------------- scratch (device globals; no allocation allowed) ----------------
__device__ __half g_xh[(size_t)T_ * H_];            // x converted to fp16
__device__ __half g_acth[(size_t)A_ * I_];          // SwiGLU activations fp16, perm order
__device__ float  g_part[(size_t)SPLITK * A_ * H_]; // split-K partials of down-proj
__device__ int    g_perm[A_];                       // assignment ids grouped by expert
__device__ int    g_offs[E_ + 1];                   // expert segment offsets
__device__ float  g_aw[A_];                         // renormalized top-2 weights

// ---------------- helpers ----------------
__device__ __forceinline__ uint32_t pack_h2(float2 v) {  // {lo=v.x, hi=v.y} as f16x2
    uint32_t r;
    asm("cvt.rn.f16x2.f32 %0, %1, %2;" : "=r"(r) : "f"(v.y), "f"(v.x));
    return r;
}
__device__ __forceinline__ void mma_f16(float* d, const uint32_t* a, const uint32_t* b) {
    asm volatile(
        "mma.sync.aligned.m16n8k16.row.col.f32.f16.f16.f32 "
        "{%0,%1,%2,%3}, {%4,%5,%6,%7}, {%8,%9}, {%0,%1,%2,%3};"
        : "+f"(d[0]), "+f"(d[1]), "+f"(d[2]), "+f"(d[3])
        : "r"(a[0]), "r"(a[1]), "r"(a[2]), "r"(a[3]), "r"(b[0]), "r"(b[1]));
}
__device__ __forceinline__ void ldsm_x4(uint32_t* r, uint32_t addr) {
    asm volatile("ldmatrix.sync.aligned.m8n8.x4.shared.b16 {%0,%1,%2,%3}, [%4];"
                 : "=r"(r[0]), "=r"(r[1]), "=r"(r[2]), "=r"(r[3]) : "r"(addr));
}
__device__ __forceinline__ uint32_t smem_u32(const void* p) {
    return (uint32_t)__cvta_generic_to_shared(p);
}
#define CP_ASYNC16(dst, src) \
    asm volatile("cp.async.cg.shared.global [%0], [%1], 16;" :: "r"(dst), "l"(src))
#define CP_COMMIT() asm volatile("cp.async.commit_group;" ::: "memory")
#define CP_WAIT(n)  asm volatile("cp.async.wait_group %0;" :: "n"(n) : "memory")

// B tile swizzle: chunk q of row n stored at position q ^ ((n&3)<<1) -> conflict-free
// LDS.64 fragment reads.
__device__ __forceinline__ uint32_t tswz(int row, int k) {
    return (uint32_t)(row * 128 + (((k >> 2) ^ ((row & 3) << 1)) << 4) + ((k & 3) << 2));
}
__device__ __forceinline__ float2 lds2(const char* base, int row, int k) {
    return *(const float2*)(base + tswz(row, k));
}

// fp16 A subtile: 128 rows x 32 halves, padded row stride 80B (conflict-free)
#define AROW 80
#define A_SUB 10240     // one 32-K A subtile
// B subtile: 256 rows x 128B = 32 KB (one 32-K slice)
#define B_SUB 32768
// Stage = K=64: A0|A1|B0|B1
#define STG (2 * A_SUB + 2 * B_SUB)   // 86016
#define NSTG 2
#define GM_SMEM (NSTG * STG + 512)    // 172544

// ---------------- x -> fp16 ----------------
__global__ void xcvt_kernel(const float* __restrict__ x) {
    int i = blockIdx.x * blockDim.x + threadIdx.x;   // over T_*H_/2 half2
    float2 v = *(const float2*)&x[2 * i];
    *(uint32_t*)&g_xh[2 * i] = pack_h2(v);
}

// ---------------- routing ----------------
__global__ void route_kernel(const float* __restrict__ logits) {
    __shared__ unsigned char s_e[A_];
    __shared__ int s_cnt[E_];
    __shared__ int s_off[E_ + 1];

    int t = threadIdx.x;
    if (t < E_) s_cnt[t] = 0;
    __syncthreads();

    float l[E_];
#pragma unroll
    for (int e = 0; e < E_; e++) l[e] = logits[t * E_ + e];

    int e0 = 0;
#pragma unroll
    for (int e = 1; e < E_; e++) if (l[e] > l[e0]) e0 = e;
    int e1 = (e0 == 0) ? 1 : 0;
#pragma unroll
    for (int e = 0; e < E_; e++) if (e != e0 && l[e] > l[e1]) e1 = e;

    float p1 = __expf(l[e1] - l[e0]);
    float inv = 1.0f / (1.0f + p1);
    g_aw[2 * t + 0] = inv;
    g_aw[2 * t + 1] = p1 * inv;

    s_e[2 * t + 0] = (unsigned char)e0;
    s_e[2 * t + 1] = (unsigned char)e1;
    atomicAdd(&s_cnt[e0], 1);
    atomicAdd(&s_cnt[e1], 1);
    __syncthreads();

    if (t == 0) {
        int acc = 0;
        for (int e = 0; e < E_; e++) { s_off[e] = acc; acc += s_cnt[e]; }
        s_off[E_] = acc;
        for (int e = 0; e <= E_; e++) g_offs[e] = s_off[e];
    }
    __syncthreads();

#pragma unroll
    for (int k = 0; k < 2; k++) {
        int a = 2 * t + k;
        int e = s_e[a];
        int rank = 0;
        for (int b = 0; b < a; b++) rank += (s_e[b] == e) ? 1 : 0;
        g_perm[s_off[e] + rank] = a;
    }
}

// ================= GEMM structure ==================================================
// CTA: M=128 x 256 B-rows, 8 warps = 2M x 4N (wm = wid>>2, SMSP-balanced),
// warp tile 64x64. K=64/stage, 2-stage cp.async.
// FULL fragment double-buffering: af and bf for kt+1 are loaded before kt's MMAs,
// so smem loads overlap tensor issue within each warp.

// =================================================================================
// GEMM1 fused: act[m, i0..i0+128) = silu(x@Wg^T)*(x@Wu^T). B rows interleaved g/u.
// =================================================================================
__global__ __launch_bounds__(256, 1)
void gemm1_fused(const float* __restrict__ w13)
{
    constexpr int NS = H_ / 64;   // 32 stages

    extern __shared__ char sm[];
    int* s_row = (int*)(sm + NSTG * STG);

    const int e = blockIdx.z;
    const int base = g_offs[e];
    const int cnt = g_offs[e + 1] - base;
    const int m0 = blockIdx.y * 128;
    if (m0 >= cnt) return;
    const int i0 = blockIdx.x * 128;   // 128 intermediates -> 256 interleaved B rows

    const int tid = threadIdx.x;
    const int wid = tid >> 5, lid = tid & 31;
    const int gid = lid >> 2, tig = lid & 3;
    const int wm = wid >> 2, wn = wid & 3;   // 2M x 4N, SMSP-balanced

    if (tid < 128) {
        int m = m0 + tid;
        int mm = (m < cnt) ? m : 0;
        s_row[tid] = g_perm[base + mm] >> 1;
    }
    __syncthreads();

    const uint32_t lmoff =
        (uint32_t)((wm * 64 + (lid & 7) + ((lid >> 3) & 1) * 8) * AROW + ((lid >> 4) & 1) * 16);

    // A: 512 chunks/subtile -> 2/thread.  B: 2048 chunks/subtile -> 8/thread.
    const char* ap[2]; uint32_t soA[2];
    const float* bp[8]; uint32_t soB[8];
#pragma unroll
    for (int t = 0; t < 2; t++) {
        int idx = t * 256 + tid;
        int row = idx >> 2, q = idx & 3;
        soA[t] = (uint32_t)(row * AROW + q * 16);
        ap[t] = (const char*)(g_xh + (size_t)s_row[row] * H_) + q * 16;
    }
#pragma unroll
    for (int t = 0; t < 8; t++) {
        int idx = t * 256 + tid;
        int row = idx >> 3, q = idx & 7;   // smem row 0..255
        soB[t] = (uint32_t)(row * 128 + ((q ^ ((row & 3) << 1)) << 4));
        int ii = i0 + (row >> 1) + ((row & 1) ? I_ : 0);   // gate/up interleave
        bp[t] = w13 + ((size_t)e * (2 * I_) + (size_t)ii) * H_ + q * 4;
    }

    const uint32_t smbase = smem_u32(sm);
    auto issue = [&](int stage) {
        uint32_t st = smbase + (uint32_t)(stage & 1) * STG;
#pragma unroll
        for (int t = 0; t < 2; t++) {
            CP_ASYNC16(st + soA[t], ap[t]);
            CP_ASYNC16(st + A_SUB + soA[t], ap[t] + 64);
            ap[t] += 128;
        }
        uint32_t bb = st + 2 * A_SUB;
#pragma unroll
        for (int t = 0; t < 8; t++) {
            CP_ASYNC16(bb + soB[t], bp[t]);
            CP_ASYNC16(bb + B_SUB + soB[t], bp[t] + 32);
            bp[t] += 64;
        }
    };

    issue(0); CP_COMMIT();

    float c[4][8][4] = {};   // 128 accum regs

    for (int s = 0; s < NS; s++) {
        CP_WAIT(0);
        __syncthreads();
        if (s + 1 < NS) issue(s + 1);
        CP_COMMIT();

        const uint32_t st = smbase + (uint32_t)(s & 1) * STG;
        const char* Bb = sm + (s & 1) * STG + 2 * A_SUB;

        uint32_t af2[2][4][4], bf2[2][8][2];
        // preload kt=0 fragments
#pragma unroll
        for (int mt = 0; mt < 4; mt++)
            ldsm_x4(af2[0][mt], st + lmoff + (uint32_t)(mt * 16 * AROW));
#pragma unroll
        for (int nt = 0; nt < 8; nt++) {
            int n = wn * 64 + nt * 8 + gid;
            bf2[0][nt][0] = pack_h2(lds2(Bb, n, 2 * tig));
            bf2[0][nt][1] = pack_h2(lds2(Bb, n, 2 * tig + 8));
        }
#pragma unroll
        for (int kt = 0; kt < 4; kt++) {           // 4 x k16 groups (K=64)
            const int cur = kt & 1, nxt = cur ^ 1;
            if (kt < 3) {                           // prefetch kt+1 (af AND bf)
                const int nksub = (kt + 1) >> 1, nkk = (kt + 1) & 1;
                const uint32_t Ab = st + (uint32_t)nksub * A_SUB;
#pragma unroll
                for (int mt = 0; mt < 4; mt++)
                    ldsm_x4(af2[nxt][mt], Ab + lmoff + (uint32_t)(mt * 16 * AROW + nkk * 32));
                const char* B = Bb + nksub * B_SUB;
                const int k0 = nkk * 16 + 2 * tig;
#pragma unroll
                for (int nt = 0; nt < 8; nt++) {
                    int n = wn * 64 + nt * 8 + gid;
                    bf2[nxt][nt][0] = pack_h2(lds2(B, n, k0));
                    bf2[nxt][nt][1] = pack_h2(lds2(B, n, k0 + 8));
                }
            }
#pragma unroll
            for (int mt = 0; mt < 4; mt++)
#pragma unroll
                for (int nt = 0; nt < 8; nt++)
                    mma_f16(c[mt][nt], af2[cur][mt], bf2[cur][nt]);
        }
    }

    // epilogue: (d0,d1) = (gate_j, up_j), j = i0 + wn*32 + nt*4 + tig
#pragma unroll
    for (int mt = 0; mt < 4; mt++) {
#pragma unroll
        for (int rr = 0; rr < 2; rr++) {
            int m = m0 + wm * 64 + mt * 16 + gid + rr * 8;
            if (m < cnt) {
                __half* op = g_acth + (size_t)(base + m) * I_ + (size_t)(i0 + wn * 32 + tig);
#pragma unroll
                for (int nt = 0; nt < 8; nt++) {
                    float g = c[mt][nt][2 * rr];
                    float u = c[mt][nt][2 * rr + 1];
                    op[nt * 4] = __float2half((g / (1.0f + __expf(-g))) * u);
                }
            }
        }
    }
}

// =================================================================================
// GEMM2 (split-K=4): part[sk][a, h0..h0+256) = act_fp16 @ w2^T.
// =================================================================================
__global__ __launch_bounds__(256, 1)
void gemm2_tc(const float* __restrict__ w2)
{
    constexpr int NS = K2_PER / 64;   // 22 stages

    extern __shared__ char sm[];
    int* s_row = (int*)(sm + NSTG * STG);

    const int e  = blockIdx.z >> 2;
    const int sk = blockIdx.z & 3;
    const int base = g_offs[e];
    const int cnt = g_offs[e + 1] - base;
    const int m0 = blockIdx.y * 128;
    if (m0 >= cnt) return;
    const int n0 = blockIdx.x * 256;
    const int koff = sk * K2_PER;

    const int tid = threadIdx.x;
    const int wid = tid >> 5, lid = tid & 31;
    const int gid = lid >> 2, tig = lid & 3;
    const int wm = wid >> 2, wn = wid & 3;   // 2M x 4N, SMSP-balanced

    if (tid < 128) {
        int m = m0 + tid;
        s_row[tid] = base + ((m < cnt) ? m : 0);
    }
    __syncthreads();

    const uint32_t lmoff =
        (uint32_t)((wm * 64 + (lid & 7) + ((lid >> 3) & 1) * 8) * AROW + ((lid >> 4) & 1) * 16);

    const char* ap[2]; uint32_t soA[2];
    const float* bp[8]; uint32_t soB[8];
#pragma unroll
    for (int t = 0; t < 2; t++) {
        int idx = t * 256 + tid;
        int row = idx >> 2, q = idx & 3;
        soA[t] = (uint32_t)(row * AROW + q * 16);
        ap[t] = (const char*)(g_acth + (size_t)s_row[row] * I_ + koff) + q * 16;
    }
#pragma unroll
    for (int t = 0; t < 8; t++) {
        int idx = t * 256 + tid;
        int row = idx >> 3, q = idx & 7;   // smem row 0..255
        soB[t] = (uint32_t)(row * 128 + ((q ^ ((row & 3) << 1)) << 4));
        bp[t] = w2 + ((size_t)e * H_ + (size_t)(n0 + row)) * I_ + koff + q * 4;
    }

    const uint32_t smbase = smem_u32(sm);
    auto issue = [&](int stage) {
        uint32_t st = smbase + (uint32_t)(stage & 1) * STG;
#pragma unroll
        for (int t = 0; t < 2; t++) {
            CP_ASYNC16(st + soA[t], ap[t]);
            CP_ASYNC16(st + A_SUB + soA[t], ap[t] + 64);
            ap[t] += 128;
        }
        uint32_t bb = st + 2 * A_SUB;
#pragma unroll
        for (int t = 0; t < 8; t++) {
            CP_ASYNC16(bb + soB[t], bp[t]);
            CP_ASYNC16(bb + B_SUB + soB[t], bp[t] + 32);
            bp[t] += 64;
        }
    };

    issue(0); CP_COMMIT();

    float c[4][8][4] = {};

    for (int s = 0; s < NS; s++) {
        CP_WAIT(0);
        __syncthreads();
        if (s + 1 < NS) issue(s + 1);
        CP_COMMIT();

        const uint32_t st = smbase + (uint32_t)(s & 1) * STG;
        const char* Bb = sm + (s & 1) * STG + 2 * A_SUB;

        uint32_t af2[2][4][4], bf2[2][8][2];
#pragma unroll
        for (int mt = 0; mt < 4; mt++)
            ldsm_x4(af2[0][mt], st + lmoff + (uint32_t)(mt * 16 * AROW));
#pragma unroll
        for (int nt = 0; nt < 8; nt++) {
            int n = wn * 64 + nt * 8 + gid;
            bf2[0][nt][0] = pack_h2(lds2(Bb, n, 2 * tig));
            bf2[0][nt][1] = pack_h2(lds2(Bb, n, 2 * tig + 8));
        }
#pragma unroll
        for (int kt = 0; kt < 4; kt++) {
            const int cur = kt & 1, nxt = cur ^ 1;
            if (kt < 3) {
                const int nksub = (kt + 1) >> 1, nkk = (kt + 1) & 1;
                const uint32_t Ab = st + (uint32_t)nksub * A_SUB;
#pragma unroll
                for (int mt = 0; mt < 4; mt++)
                    ldsm_x4(af2[nxt][mt], Ab + lmoff + (uint32_t)(mt * 16 * AROW + nkk * 32));
                const char* B = Bb + nksub * B_SUB;
                const int k0 = nkk * 16 + 2 * tig;
#pragma unroll
                for (int nt = 0; nt < 8; nt++) {
                    int n = wn * 64 + nt * 8 + gid;
                    bf2[nxt][nt][0] = pack_h2(lds2(B, n, k0));
                    bf2[nxt][nt][1] = pack_h2(lds2(B, n, k0 + 8));
                }
            }
#pragma unroll
            for (int mt = 0; mt < 4; mt++)
#pragma unroll
                for (int nt = 0; nt < 8; nt++)
                    mma_f16(c[mt][nt], af2[cur][mt], bf2[cur][nt]);
        }
    }

    // epilogue: write split partial (assignment-id rows)
    float* part = g_part + (size_t)sk * A_ * H_;
#pragma unroll
    for (int mt = 0; mt < 4; mt++) {
#pragma unroll
        for (int rr = 0; rr < 2; rr++) {
            int m = m0 + wm * 64 + mt * 16 + gid + rr * 8;
            if (m < cnt) {
                int orow = g_perm[base + m];
                float* op = part + (size_t)orow * H_ + (size_t)(n0 + wn * 64) + 2 * tig;
#pragma unroll
                for (int nt = 0; nt < 8; nt++) {
                    float2 v = make_float2(c[mt][nt][2 * rr], c[mt][nt][2 * rr + 1]);
                    *(float2*)(op + nt * 8) = v;
                }
            }
        }
    }
}

// ---------------- combine: out[t,h] = sum_k aw * sum_s part[s][2t+k][h] -----------
__global__ void combine_kernel(float* __restrict__ out) {
    int idx = blockIdx.x * blockDim.x + threadIdx.x;
    int t  = idx >> 9;
    int h4 = idx & 511;
    float w0 = g_aw[2 * t];
    float w1 = g_aw[2 * t + 1];
    size_t o0 = (size_t)(2 * t) * H_ + (size_t)h4 * 4;
    size_t o1 = (size_t)(2 * t + 1) * H_ + (size_t)h4 * 4;

    float4 a0 = make_float4(0.f, 0.f, 0.f, 0.f);
    float4 a1 = make_float4(0.f, 0.f, 0.f, 0.f);
#pragma unroll
    for (int s = 0; s < SPLITK; s++) {   // fixed order -> deterministic
        const float* p = g_part + (size_t)s * A_ * H_;
        float4 v0 = *(const float4*)(p + o0);
        float4 v1 = *(const float4*)(p + o1);
        a0.x += v0.x; a0.y += v0.y; a0.z += v0.z; a0.w += v0.w;
        a1.x += v1.x; a1.y += v1.y; a1.z += v1.z; a1.w += v1.w;
    }
    float4 o;
    o.x = w0 * a0.x + w1 * a1.x;
    o.y = w0 * a0.y + w1 * a1.y;
    o.z = w0 * a0.z + w1 * a1.z;
    o.w = w0 * a0.w + w1 * a1.w;
    *(float4*)&out[(size_t)t * H_ + (size_t)h4 * 4] = o;
}

extern "C" void kernel_launch(void* const* d_in, const int* in_sizes, int n_in,
                              void* d_out, int out_size) {
    const float* x   = (const float*)d_in[0];   // [512, 2048]
    const float* rl  = (const float*)d_in[1];   // [512, 8]
    const float* w13 = (const float*)d_in[2];   // [8, 11264, 2048]
    const float* w2  = (const float*)d_in[3];   // [8, 2048, 5632]
    float* out = (float*)d_out;                 // [512, 2048]
    (void)in_sizes; (void)n_in; (void)out_size;

    cudaFuncSetAttribute(gemm1_fused, cudaFuncAttributeMaxDynamicSharedMemorySize, GM_SMEM);
    cudaFuncSetAttribute(gemm2_tc,    cudaFuncAttributeMaxDynamicSharedMemorySize, GM_SMEM);

    xcvt_kernel<<<(T_ * H_ / 2) / 256, 256>>>(x);
    route_kernel<<<1, T_>>>(rl);
    // GEMM1 fused: 44 i-tiles x 4 M-blocks x 8 experts
    gemm1_fused<<<dim3(I_ / 128, 4, E_), 256, GM_SMEM>>>(w13);
    // GEMM2 split-K: 8 h-tiles x 4 M-blocks x (e*4+sk)
    gemm2_tc<<<dim3(H_ / 256, 4, E_ * SPLITK), 256, GM_SMEM>>>(w2);
    combine_kernel<<<(T_ * H_ / 4) / 512, 512>>>(out);
}